// round 2
// baseline (speedup 1.0000x reference)
#include <cuda_runtime.h>

// CubicalModel_ISM: out[j]     = dot(X[r1(j)], p), r1(j) = inds1[2j]*28 + inds1[2j+1], j in [0,100)
//                   out[100+j] = dot(Y[r2(j)], p)
// Only 200 of 1568 rows are needed. Phase 1: 200 dots x 8 segments = 1600 blocks,
// each block reduces a 1024-float4 segment to one partial. Phase 2: sum partials.

#define Q       32768
#define QV      (Q / 4)        // 8192 float4 per row
#define SPLIT   8
#define SEG     (QV / SPLIT)   // 1024 float4 per block
#define NT      256
#define W_DIM   28
#define NDOTS   200

__device__ float g_partial[NDOTS * SPLIT];

__global__ __launch_bounds__(NT)
void dot_partial_kernel(const float* __restrict__ X,
                        const float* __restrict__ Y,
                        const float* __restrict__ p,
                        const int*   __restrict__ inds1,
                        const int*   __restrict__ inds2)
{
    const int b   = blockIdx.x;          // 0..1599
    const int j   = b >> 3;              // dot index 0..199
    const int seg = b & (SPLIT - 1);     // segment 0..7

    const bool second = (j >= 100);
    const int jj = second ? (j - 100) : j;
    const int* __restrict__ inds = second ? inds2 : inds1;
    const float* __restrict__ M  = second ? Y : X;

    const int r = inds[2 * jj] * W_DIM + inds[2 * jj + 1];

    const float4* __restrict__ row = reinterpret_cast<const float4*>(M + (size_t)r * Q);
    const float4* __restrict__ pv  = reinterpret_cast<const float4*>(p);

    const int i0 = seg * SEG + threadIdx.x;

    // Front-batched independent loads: 8x LDG.128 in flight (MLP=8)
    float4 a0 = row[i0];
    float4 a1 = row[i0 +     NT];
    float4 a2 = row[i0 + 2 * NT];
    float4 a3 = row[i0 + 3 * NT];
    float4 b0 = pv [i0];
    float4 b1 = pv [i0 +     NT];
    float4 b2 = pv [i0 + 2 * NT];
    float4 b3 = pv [i0 + 3 * NT];

    float sum = a0.x * b0.x + a0.y * b0.y + a0.z * b0.z + a0.w * b0.w;
    sum += a1.x * b1.x + a1.y * b1.y + a1.z * b1.z + a1.w * b1.w;
    sum += a2.x * b2.x + a2.y * b2.y + a2.z * b2.z + a2.w * b2.w;
    sum += a3.x * b3.x + a3.y * b3.y + a3.z * b3.z + a3.w * b3.w;

    // warp reduce
    #pragma unroll
    for (int off = 16; off > 0; off >>= 1)
        sum += __shfl_xor_sync(0xFFFFFFFFu, sum, off);

    __shared__ float warp_sums[NT / 32];
    const int lane = threadIdx.x & 31;
    const int wid  = threadIdx.x >> 5;
    if (lane == 0) warp_sums[wid] = sum;
    __syncthreads();

    if (wid == 0) {
        float s = (lane < NT / 32) ? warp_sums[lane] : 0.0f;
        #pragma unroll
        for (int off = 4; off > 0; off >>= 1)
            s += __shfl_xor_sync(0xFFFFFFFFu, s, off);
        if (lane == 0) g_partial[b] = s;
    }
}

__global__ void reduce_kernel(float* __restrict__ out)
{
    const int j = threadIdx.x;
    if (j < NDOTS) {
        float s = 0.0f;
        #pragma unroll
        for (int k = 0; k < SPLIT; k++)
            s += g_partial[j * SPLIT + k];
        out[j] = s;
    }
}

extern "C" void kernel_launch(void* const* d_in, const int* in_sizes, int n_in,
                              void* d_out, int out_size)
{
    const float* X   = (const float*)d_in[0];
    const float* Y   = (const float*)d_in[1];
    const float* p   = (const float*)d_in[2];
    const int* inds1 = (const int*)d_in[3];
    const int* inds2 = (const int*)d_in[4];
    float* out       = (float*)d_out;

    dot_partial_kernel<<<NDOTS * SPLIT, NT>>>(X, Y, p, inds1, inds2);
    reduce_kernel<<<1, 256>>>(out);
}